// round 2
// baseline (speedup 1.0000x reference)
#include <cuda_runtime.h>
#include <cstdint>

#define BATCHES 64
#define NPTS    (1<<18)
#define NCL     8
#define NITER   10
#define CAND_CAP 1024
#define K2_THRESH (1u<<22)

__device__ unsigned g_key1[(size_t)BATCHES * NPTS];
__device__ unsigned long long g_cand[BATCHES * CAND_CAP];
__device__ int g_cand_cnt[BATCHES];
__device__ uint2 g_sub1[BATCHES], g_sub2[BATCHES];
__device__ float g_cent[BATCHES * NCL * 3];
__device__ float g_sums[BATCHES * NCL * 4];

__device__ __forceinline__ void tf2x32(unsigned k0, unsigned k1,
                                       unsigned x0, unsigned x1,
                                       unsigned &o0, unsigned &o1) {
  unsigned k2 = k0 ^ k1 ^ 0x1BD11BDAu;
  x0 += k0; x1 += k1;
#define TF_R(r) { x0 += x1; x1 = __funnelshift_l(x1, x1, (r)); x1 ^= x0; }
  TF_R(13) TF_R(15) TF_R(26) TF_R(6)  x0 += k1; x1 += k2 + 1u;
  TF_R(17) TF_R(29) TF_R(16) TF_R(24) x0 += k2; x1 += k0 + 2u;
  TF_R(13) TF_R(15) TF_R(26) TF_R(6)  x0 += k0; x1 += k1 + 3u;
  TF_R(17) TF_R(29) TF_R(16) TF_R(24) x0 += k1; x1 += k2 + 4u;
  TF_R(13) TF_R(15) TF_R(26) TF_R(6)  x0 += k2; x1 += k0 + 5u;
#undef TF_R
  o0 = x0; o1 = x1;
}

// per-batch shuffle subkeys (threefry_partitionable scheme)
__global__ void k_init() {
  int b = threadIdx.x;
  if (b >= BATCHES) return;
  unsigned a0, a1, n0, n1, s0, s1;
  tf2x32(0u, 42u, 0u, (unsigned)b, a0, a1);   // keys[b] = split(key(42),64)[b]
  tf2x32(a0, a1, 0u, 0u, n0, n1);             // key'  = split(key_b)[0]
  tf2x32(a0, a1, 0u, 1u, s0, s1);             // sub1  = split(key_b)[1]
  g_sub1[b] = make_uint2(s0, s1);
  tf2x32(n0, n1, 0u, 1u, s0, s1);             // sub2  = split(key')[1]
  g_sub2[b] = make_uint2(s0, s1);
  g_cand_cnt[b] = 0;
}

// round-1 sort keys (stored) + round-2 key candidate filter
__global__ void k_gen() {
  unsigned stride = gridDim.x * blockDim.x;
  for (unsigned idx = blockIdx.x * blockDim.x + threadIdx.x;
       idx < (unsigned)BATCHES * NPTS; idx += stride) {
    int b = idx >> 18;
    unsigned i = idx & (NPTS - 1);
    uint2 s1 = g_sub1[b], s2 = g_sub2[b];
    unsigned y0, y1;
    tf2x32(s1.x, s1.y, 0u, i, y0, y1);
    g_key1[idx] = y0 ^ y1;                      // random_bits fold
    tf2x32(s2.x, s2.y, 0u, i, y0, y1);
    unsigned k2v = y0 ^ y1;
    if (k2v < K2_THRESH) {
      int slot = atomicAdd(&g_cand_cnt[b], 1);
      if (slot < CAND_CAP)
        g_cand[b * CAND_CAP + slot] = ((unsigned long long)k2v << 32) | i;
    }
  }
}

// top-8 (key2,pos) -> ranks; radix rank-select on (key1,idx) -> init centroids
__global__ void __launch_bounds__(1024) k_select(const float* __restrict__ in) {
  int b = blockIdx.x;
  int t = threadIdx.x;
  int lane = t & 31, wid = t >> 5;
  __shared__ unsigned long long s_cand[CAND_CAP];
  __shared__ unsigned s_whist[32][256];
  __shared__ unsigned s_h[256];
  __shared__ unsigned long long s_list[8][64];
  __shared__ int s_lcnt[8];
  __shared__ int s_rank[8];
  __shared__ unsigned s_pfx[8];
  __shared__ unsigned s_v[8];
  __shared__ unsigned long long s_min;

  // Phase A: 8 smallest (key2,pos); pos = target ranks into round-1 order
  int cnt = g_cand_cnt[b]; if (cnt > CAND_CAP) cnt = CAND_CAP;
  s_cand[t] = (t < cnt) ? g_cand[b * CAND_CAP + t] : ~0ull;
  __syncthreads();
  for (int k = 0; k < 8; ++k) {
    if (t == 0) s_min = ~0ull;
    __syncthreads();
    atomicMin(&s_min, s_cand[t]);
    __syncthreads();
    unsigned long long m = s_min;
    if (t == 0) { s_rank[k] = (int)(m & 0xffffffffull); s_pfx[k] = 0u; s_lcnt[k] = 0; }
    if (s_cand[t] == m) s_cand[t] = ~0ull;
    __syncthreads();
  }

  const unsigned* __restrict__ keyp = g_key1 + (size_t)b * NPTS;

  // Pass 0: MSB-byte histogram (warp-private, match_any)
  for (int i = lane; i < 256; i += 32) s_whist[wid][i] = 0u;
  __syncthreads();
  for (int i = t; i < NPTS; i += 1024) {
    unsigned k = keyp[i];
    unsigned bt = k >> 24;
    unsigned mm = __match_any_sync(0xffffffffu, bt);
    if (lane == (__ffs(mm) - 1)) s_whist[wid][bt] += __popc(mm);
  }
  __syncthreads();
  if (t < 256) {
    unsigned s = 0;
    for (int w = 0; w < 32; ++w) s += s_whist[w][t];
    s_h[t] = s;
  }
  __syncthreads();
  if (t < 8) {
    int r = s_rank[t], cum = 0, d = 0;
    for (; d < 256; ++d) { int h = (int)s_h[d]; if (cum + h > r) break; cum += h; }
    s_rank[t] = r - cum; s_pfx[t] = (unsigned)d << 24;
  }
  __syncthreads();

  // Pass 1: byte2 histogram conditioned on MSB (rare hits -> atomics fine)
  for (int i = t; i < 8 * 256; i += 1024) (&s_whist[0][0])[i] = 0u;
  __syncthreads();
  unsigned pf[8];
  #pragma unroll
  for (int j = 0; j < 8; ++j) pf[j] = s_pfx[j];
  for (int i = t; i < NPTS; i += 1024) {
    unsigned k = keyp[i];
    unsigned top = k & 0xFF000000u;
    #pragma unroll
    for (int j = 0; j < 8; ++j)
      if (top == pf[j]) atomicAdd(&s_whist[j][(k >> 16) & 255u], 1u);
  }
  __syncthreads();
  if (t < 8) {
    int r = s_rank[t], cum = 0, d = 0;
    for (; d < 256; ++d) { int h = (int)s_whist[t][d]; if (cum + h > r) break; cum += h; }
    s_rank[t] = r - cum; s_pfx[t] |= (unsigned)d << 16;
  }
  __syncthreads();

  // Pass 2: collect 16-bit-prefix matches, select rank within by (low16,idx)
  #pragma unroll
  for (int j = 0; j < 8; ++j) pf[j] = s_pfx[j];
  for (int i = t; i < NPTS; i += 1024) {
    unsigned k = keyp[i];
    unsigned top = k & 0xFFFF0000u;
    #pragma unroll
    for (int j = 0; j < 8; ++j)
      if (top == pf[j]) {
        int s = atomicAdd(&s_lcnt[j], 1);
        if (s < 64) s_list[j][s] = ((unsigned long long)(k & 0xFFFFu) << 32) | (unsigned)i;
      }
  }
  __syncthreads();
  if (t < 8) {
    int n = s_lcnt[t]; if (n > 64) n = 64;
    int r = s_rank[t];
    unsigned long long last = 0ull; bool first = true;
    for (int step = 0; step <= r && step < n; ++step) {
      unsigned long long mn = ~0ull;
      for (int q = 0; q < n; ++q) {
        unsigned long long v = s_list[t][q];
        if ((first || v > last) && v < mn) mn = v;
      }
      last = mn; first = false;
    }
    s_v[t] = (unsigned)(last & 0xffffffffull);
  }
  __syncthreads();
  if (t < 8) {
    const float* px = in + ((size_t)b * NPTS + s_v[t]) * 3;
    float* c = g_cent + (b * NCL + t) * 3;
    c[0] = px[0]; c[1] = px[1]; c[2] = px[2];
  }
  if (t < 32) g_sums[b * 32 + t] = 0.f;
}

// Lloyd assignment + partial sums. 32 blocks/batch, 8192 pts/block.
__global__ void __launch_bounds__(256) k_assign(const float* __restrict__ in) {
  int b   = blockIdx.x >> 5;
  int blk = blockIdx.x & 31;
  int tid = threadIdx.x;
  __shared__ float4 s_st[768];         // 1024-pt stage (12 KB)
  __shared__ float  s_acc[32][256];    // [cluster*4+comp][tid] (32 KB)

  float n0[8], n1[8], n2[8], bb[8];
  const float* cent = g_cent + b * 24;
  #pragma unroll
  for (int c = 0; c < 8; ++c) {
    float a = cent[c*3+0], d = cent[c*3+1], e = cent[c*3+2];
    n0[c] = -2.f*a; n1[c] = -2.f*d; n2[c] = -2.f*e;
    bb[c] = a*a + d*d + e*e;           // argmin ||x-c||^2 == argmin(||c||^2 - 2x.c)
  }
  for (int i = tid; i < 32*256; i += 256) (&s_acc[0][0])[i] = 0.f;

  const float4* gp = (const float4*)in + (size_t)b * (NPTS*3/4) + (size_t)blk * 6144;
  for (int ch = 0; ch < 8; ++ch) {
    __syncthreads();
    const float4* src = gp + ch * 768;
    s_st[tid]       = src[tid];
    s_st[tid + 256] = src[tid + 256];
    s_st[tid + 512] = src[tid + 512];
    __syncthreads();
    const float* sf = (const float*)s_st;
    #pragma unroll
    for (int q = 0; q < 4; ++q) {
      int p = q * 256 + tid;
      float x0 = sf[p*3+0], x1 = sf[p*3+1], x2 = sf[p*3+2];
      float best = 3.4e38f; int bi = 0;
      #pragma unroll
      for (int c = 0; c < 8; ++c) {
        float s = bb[c];
        s = fmaf(x0, n0[c], s);
        s = fmaf(x1, n1[c], s);
        s = fmaf(x2, n2[c], s);
        if (s < best) { best = s; bi = c; }   // strict <: first-min like argmin
      }
      s_acc[bi*4+0][tid] += x0;
      s_acc[bi*4+1][tid] += x1;
      s_acc[bi*4+2][tid] += x2;
      s_acc[bi*4+3][tid] += 1.f;
    }
  }
  __syncthreads();
  int wid = tid >> 5, lane = tid & 31;   // warp w reduces cluster w
  float r0=0.f, r1=0.f, r2=0.f, r3=0.f;
  for (int i = lane; i < 256; i += 32) {
    r0 += s_acc[wid*4+0][i];
    r1 += s_acc[wid*4+1][i];
    r2 += s_acc[wid*4+2][i];
    r3 += s_acc[wid*4+3][i];
  }
  #pragma unroll
  for (int o = 16; o; o >>= 1) {
    r0 += __shfl_down_sync(0xffffffffu, r0, o);
    r1 += __shfl_down_sync(0xffffffffu, r1, o);
    r2 += __shfl_down_sync(0xffffffffu, r2, o);
    r3 += __shfl_down_sync(0xffffffffu, r3, o);
  }
  if (lane == 0) {
    float* gs = g_sums + b * 32 + wid * 4;
    atomicAdd(gs+0, r0); atomicAdd(gs+1, r1);
    atomicAdd(gs+2, r2); atomicAdd(gs+3, r3);
  }
}

// new centroids from sums; re-zero sums; optionally emit to d_out
__global__ void k_update(float* __restrict__ out, int write_out) {
  int b = blockIdx.x, t = threadIdx.x;   // 8 threads: each owns one cluster
  if (t < 8) {
    float* s = g_sums + b * 32 + t * 4;
    float sx = s[0], sy = s[1], sz = s[2], c = s[3];
    float* cc = g_cent + (b * NCL + t) * 3;
    if (c > 0.f) { cc[0] = sx / c; cc[1] = sy / c; cc[2] = sz / c; }
    s[0] = 0.f; s[1] = 0.f; s[2] = 0.f; s[3] = 0.f;
    if (write_out) {
      out[b * 24 + t * 3 + 0] = cc[0];
      out[b * 24 + t * 3 + 1] = cc[1];
      out[b * 24 + t * 3 + 2] = cc[2];
    }
  }
}

extern "C" void kernel_launch(void* const* d_in, const int* in_sizes, int n_in,
                              void* d_out, int out_size) {
  const float* in = (const float*)d_in[0];
  float* out = (float*)d_out;
  k_init<<<1, 64>>>();
  k_gen<<<4096, 256>>>();
  k_select<<<BATCHES, 1024>>>(in);
  for (int it = 0; it < NITER; ++it) {
    k_assign<<<BATCHES * 32, 256>>>(in);
    k_update<<<BATCHES, 32>>>(out, it == NITER - 1 ? 1 : 0);
  }
}